// round 1
// baseline (speedup 1.0000x reference)
#include <cuda_runtime.h>
#include <math.h>

#define B_   64
#define T_   200
#define TP1_ 201
#define D_   128
#define M_   64
#define NQ_  13523
#define BT_  (B_*T_)          // 12800

// ---------------- scratch (no allocation allowed) ----------------
__device__ float g_k  [BT_*D_];
__device__ float g_w  [BT_*M_];
__device__ float g_e  [BT_*D_];
__device__ float g_a  [BT_*D_];
__device__ float g_rp0[BT_*D_];
__device__ float g_rp1[BT_*D_];

__device__ __forceinline__ float sigmoidf_(float x) { return 1.0f/(1.0f+expf(-x)); }

// =================================================================
// Kernel 1: k gather + w = softmax(k @ Mk^T)   (also stores k to g_k)
// 64 rows/block, 128 threads, 4x4 register blocking
// =================================================================
#define K1_SX  0
#define K1_SWT (64*128)
#define K1_SC  (K1_SWT + 32*132)
#define K1_SQ  (K1_SC + 64*65)
#define K1_SMEM ((K1_SQ + 64)*4)

__global__ void __launch_bounds__(128) k_wsoft(const int* __restrict__ q,
                                               const float* __restrict__ k_emb,
                                               const float* __restrict__ Mk) {
    extern __shared__ float sm[];
    float* sx  = sm + K1_SX;
    float* swt = sm + K1_SWT;
    float* sc  = sm + K1_SC;
    int*   sq  = (int*)(sm + K1_SQ);
    const int tid  = threadIdx.x;
    const int row0 = blockIdx.x * 64;

    if (tid < 64) sq[tid] = q[row0 + tid];
    __syncthreads();

    const int col  = (tid & 31) * 4;
    const int rsub = tid >> 5;
#pragma unroll
    for (int it = 0; it < 16; it++) {
        int r = it * 4 + rsub;
        float4 kv = *(const float4*)(k_emb + (size_t)sq[r] * D_ + col);
        *(float4*)(sx + r * D_ + col) = kv;
        *(float4*)(g_k + (size_t)(row0 + r) * D_ + col) = kv;
    }

    const int rg = tid >> 3, ng = tid & 7;
    for (int mc = 0; mc < 2; mc++) {
        __syncthreads();
#pragma unroll
        for (int it = 0; it < 8; it++) {
            int n = it * 4 + rsub;
            *(float4*)(swt + n * 132 + col) = *(const float4*)(Mk + (size_t)(mc*32 + n) * D_ + col);
        }
        __syncthreads();
        float acc[4][4] = {};
        for (int j = 0; j < D_; j += 4) {
            float4 av[4], bv[4];
#pragma unroll
            for (int i = 0; i < 4; i++) av[i] = *(float4*)(sx + (rg*4+i)*D_ + j);
#pragma unroll
            for (int c = 0; c < 4; c++) bv[c] = *(float4*)(swt + (ng*4+c)*132 + j);
#pragma unroll
            for (int i = 0; i < 4; i++)
#pragma unroll
                for (int c = 0; c < 4; c++) {
                    acc[i][c] = fmaf(av[i].x, bv[c].x, acc[i][c]);
                    acc[i][c] = fmaf(av[i].y, bv[c].y, acc[i][c]);
                    acc[i][c] = fmaf(av[i].z, bv[c].z, acc[i][c]);
                    acc[i][c] = fmaf(av[i].w, bv[c].w, acc[i][c]);
                }
        }
#pragma unroll
        for (int i = 0; i < 4; i++)
#pragma unroll
            for (int c = 0; c < 4; c++)
                sc[(rg*4+i)*65 + mc*32 + ng*4 + c] = acc[i][c];
    }
    __syncthreads();
    if (tid < 64) {
        float mx = -1e30f;
#pragma unroll
        for (int m = 0; m < M_; m++) mx = fmaxf(mx, sc[tid*65 + m]);
        float s = 0.f;
#pragma unroll
        for (int m = 0; m < M_; m++) {
            float e = expf(sc[tid*65 + m] - mx);
            sc[tid*65 + m] = e;
            s += e;
        }
        float inv = 1.0f / s;
#pragma unroll
        for (int m = 0; m < M_; m++)
            g_w[(size_t)(row0 + tid)*M_ + m] = sc[tid*65 + m] * inv;
    }
}

// =================================================================
// Kernel 2: v gather + e = sigmoid(v@eW^T+eb), a = tanh(v@aW^T+ab)
// =================================================================
#define K2_SX  0
#define K2_SWT (64*128)
#define K2_SQ  (K2_SWT + 32*132)
#define K2_SMEM ((K2_SQ + 64)*4)

__global__ void __launch_bounds__(128) k_ea(const int* __restrict__ q, const int* __restrict__ rr,
                                            const float* __restrict__ v_emb,
                                            const float* __restrict__ eW, const float* __restrict__ ebv,
                                            const float* __restrict__ aW, const float* __restrict__ abv) {
    extern __shared__ float sm[];
    float* sx  = sm + K2_SX;
    float* swt = sm + K2_SWT;
    int*   sq  = (int*)(sm + K2_SQ);
    const int tid  = threadIdx.x;
    const int row0 = blockIdx.x * 64;

    if (tid < 64) { int row = row0 + tid; sq[tid] = q[row] + NQ_ * rr[row]; }
    __syncthreads();

    const int col  = (tid & 31) * 4;
    const int rsub = tid >> 5;
#pragma unroll
    for (int it = 0; it < 16; it++) {
        int r = it * 4 + rsub;
        *(float4*)(sx + r * D_ + col) = *(const float4*)(v_emb + (size_t)sq[r] * D_ + col);
    }

    const int rg = tid >> 3, ng = tid & 7;
    for (int nc = 0; nc < 8; nc++) {
        const float* W    = (nc < 4) ? eW  : aW;
        const float* bias = (nc < 4) ? ebv : abv;
        const int nb = (nc & 3) * 32;
        __syncthreads();
#pragma unroll
        for (int it = 0; it < 8; it++) {
            int n = it * 4 + rsub;
            *(float4*)(swt + n * 132 + col) = *(const float4*)(W + (size_t)(nb + n) * D_ + col);
        }
        __syncthreads();
        float acc[4][4] = {};
        for (int j = 0; j < D_; j += 4) {
            float4 av[4], bv[4];
#pragma unroll
            for (int i = 0; i < 4; i++) av[i] = *(float4*)(sx + (rg*4+i)*D_ + j);
#pragma unroll
            for (int c = 0; c < 4; c++) bv[c] = *(float4*)(swt + (ng*4+c)*132 + j);
#pragma unroll
            for (int i = 0; i < 4; i++)
#pragma unroll
                for (int c = 0; c < 4; c++) {
                    acc[i][c] = fmaf(av[i].x, bv[c].x, acc[i][c]);
                    acc[i][c] = fmaf(av[i].y, bv[c].y, acc[i][c]);
                    acc[i][c] = fmaf(av[i].z, bv[c].z, acc[i][c]);
                    acc[i][c] = fmaf(av[i].w, bv[c].w, acc[i][c]);
                }
        }
        const int n0 = nb + ng * 4;
        float b0 = bias[n0+0], b1 = bias[n0+1], b2 = bias[n0+2], b3 = bias[n0+3];
#pragma unroll
        for (int i = 0; i < 4; i++) {
            size_t row = (size_t)(row0 + rg*4 + i);
            float4 o;
            if (nc < 4) {
                o.x = sigmoidf_(acc[i][0] + b0); o.y = sigmoidf_(acc[i][1] + b1);
                o.z = sigmoidf_(acc[i][2] + b2); o.w = sigmoidf_(acc[i][3] + b3);
                *(float4*)(g_e + row * D_ + n0) = o;
            } else {
                o.x = tanhf(acc[i][0] + b0); o.y = tanhf(acc[i][1] + b1);
                o.z = tanhf(acc[i][2] + b2); o.w = tanhf(acc[i][3] + b3);
                *(float4*)(g_a + row * D_ + n0) = o;
            }
        }
    }
}

// =================================================================
// Kernel 3: sequential scan over t. grid (B, 2 m-chunks), 128 thr (one d each).
// Per-thread state Mv[32] in registers. Writes Mv slices (the 421MB) + partial reads.
// =================================================================
__global__ void __launch_bounds__(128) k_scan(const float* __restrict__ Mv0, float* __restrict__ out) {
    const int b   = blockIdx.x;
    const int mc  = blockIdx.y;
    const int tid = threadIdx.x;   // d
    const int m0  = mc * 32;
    __shared__ float swb[2][32];
    float Mv[32];

    float* mvout = out + BT_ + (size_t)b * TP1_ * M_ * D_;
#pragma unroll
    for (int i = 0; i < 32; i++) {
        float v = Mv0[(m0 + i) * D_ + tid];
        Mv[i] = v;
        mvout[(size_t)(m0 + i) * D_ + tid] = v;     // t = 0 (init) slice
    }

    const float* wb  = g_w + (size_t)b * T_ * M_ + m0;
    const float* ebp = g_e + (size_t)b * T_ * D_ + tid;
    const float* abp = g_a + (size_t)b * T_ * D_ + tid;
    float* rp = (mc ? g_rp1 : g_rp0) + (size_t)b * T_ * D_ + tid;

    float wreg = 0.f;
    if (tid < 32) {
        swb[0][tid] = wb[tid];          // w_0
        wreg        = wb[M_ + tid];     // w_1 prefetched
    }
    float ecur = ebp[0], acur = abp[0];
    float* orow = mvout + (size_t)M_ * D_ + (size_t)m0 * D_ + tid;   // slice t+1 base

    for (int t = 0; t < T_; t++) {
        float enx = ecur, anx = acur;
        if (t + 1 < T_) { enx = ebp[(size_t)(t+1)*D_]; anx = abp[(size_t)(t+1)*D_]; }
        __syncthreads();
        if (tid < 32) {
            if (t + 1 < T_) swb[(t+1)&1][tid] = wreg;                 // publish w_{t+1}
            if (t + 2 < T_) wreg = wb[(size_t)(t+2)*M_ + tid];        // prefetch w_{t+2}
        }
        const float* wrow = swb[t & 1];
        float racc = 0.f;
#pragma unroll
        for (int i = 0; i < 32; i++) {
            float wv = wrow[i];
            racc  = fmaf(wv, Mv[i], racc);                            // read uses OLD Mv
            Mv[i] = fmaf(wv, acur, Mv[i] * fmaf(-wv, ecur, 1.0f));    // Mv*(1-w e)+w a
            orow[(size_t)i * D_] = Mv[i];
        }
        rp[(size_t)t * D_] = racc;
        ecur = enx; acur = anx;
        orow += (size_t)M_ * D_;
    }
}

// =================================================================
// Kernel 4: read = rp0+rp1; f = tanh([read,k]@fW^T + fb); p = sigmoid(f·pW + pb)
// p folded into epilogue, f never materialized to gmem.
// =================================================================
#define K4_SX  0                      // 64*256
#define K4_SWT (64*256)               // 32*260
#define K4_SP  (K4_SWT + 32*260)      // 64*8
#define K4_SMEM ((K4_SP + 64*8)*4)

__global__ void __launch_bounds__(128) k_fp(const float* __restrict__ fW, const float* __restrict__ fb,
                                            const float* __restrict__ pW, const float* __restrict__ pb,
                                            float* __restrict__ out) {
    extern __shared__ float sm[];
    float* sx  = sm + K4_SX;
    float* swt = sm + K4_SWT;
    float* sp  = sm + K4_SP;
    const int tid  = threadIdx.x;
    const int row0 = blockIdx.x * 64;
    const int col  = (tid & 31) * 4;
    const int rsub = tid >> 5;

#pragma unroll
    for (int it = 0; it < 16; it++) {
        int r = it * 4 + rsub;
        size_t g = (size_t)(row0 + r) * D_ + col;
        float4 r0 = *(const float4*)(g_rp0 + g);
        float4 r1 = *(const float4*)(g_rp1 + g);
        float4 rd; rd.x = r0.x + r1.x; rd.y = r0.y + r1.y; rd.z = r0.z + r1.z; rd.w = r0.w + r1.w;
        *(float4*)(sx + r * 256 + col)       = rd;                       // read part
        *(float4*)(sx + r * 256 + 128 + col) = *(const float4*)(g_k + g); // k part
    }

    const int rg = tid >> 3, ng = tid & 7;
    float ps[4] = {};
    for (int nc = 0; nc < 4; nc++) {
        __syncthreads();
#pragma unroll
        for (int it = 0; it < 16; it++) {
            int r  = it * 2 + (tid >> 6);
            int c2 = (tid & 63) * 4;
            *(float4*)(swt + r * 260 + c2) = *(const float4*)(fW + (size_t)(nc*32 + r) * 256 + c2);
        }
        __syncthreads();
        float acc[4][4] = {};
        for (int j = 0; j < 256; j += 4) {
            float4 av[4], bv[4];
#pragma unroll
            for (int i = 0; i < 4; i++) av[i] = *(float4*)(sx + (rg*4+i)*256 + j);
#pragma unroll
            for (int c = 0; c < 4; c++) bv[c] = *(float4*)(swt + (ng*4+c)*260 + j);
#pragma unroll
            for (int i = 0; i < 4; i++)
#pragma unroll
                for (int c = 0; c < 4; c++) {
                    acc[i][c] = fmaf(av[i].x, bv[c].x, acc[i][c]);
                    acc[i][c] = fmaf(av[i].y, bv[c].y, acc[i][c]);
                    acc[i][c] = fmaf(av[i].z, bv[c].z, acc[i][c]);
                    acc[i][c] = fmaf(av[i].w, bv[c].w, acc[i][c]);
                }
        }
#pragma unroll
        for (int c = 0; c < 4; c++) {
            int n = nc*32 + ng*4 + c;
            float w  = pW[n];
            float bb = fb[n];
#pragma unroll
            for (int i = 0; i < 4; i++)
                ps[i] = fmaf(w, tanhf(acc[i][c] + bb), ps[i]);
        }
    }
#pragma unroll
    for (int i = 0; i < 4; i++) sp[(rg*4+i)*8 + ng] = ps[i];
    __syncthreads();
    if (tid < 64) {
        float s = pb[0];
#pragma unroll
        for (int g2 = 0; g2 < 8; g2++) s += sp[tid*8 + g2];
        out[row0 + tid] = 1.0f / (1.0f + expf(-s));
    }
}

// =================================================================
extern "C" void kernel_launch(void* const* d_in, const int* in_sizes, int n_in,
                              void* d_out, int out_size) {
    const int*   q     = (const int*)  d_in[0];
    const int*   r     = (const int*)  d_in[1];
    const float* k_emb = (const float*)d_in[2];
    const float* v_emb = (const float*)d_in[3];
    const float* Mk    = (const float*)d_in[4];
    const float* Mv0   = (const float*)d_in[5];
    const float* fW    = (const float*)d_in[6];
    const float* fb    = (const float*)d_in[7];
    const float* pW    = (const float*)d_in[8];
    const float* pb    = (const float*)d_in[9];
    const float* eW    = (const float*)d_in[10];
    const float* eb    = (const float*)d_in[11];
    const float* aW    = (const float*)d_in[12];
    const float* ab    = (const float*)d_in[13];
    float* out = (float*)d_out;

    cudaFuncSetAttribute(k_wsoft, cudaFuncAttributeMaxDynamicSharedMemorySize, K1_SMEM);
    cudaFuncSetAttribute(k_ea,    cudaFuncAttributeMaxDynamicSharedMemorySize, K2_SMEM);
    cudaFuncSetAttribute(k_fp,    cudaFuncAttributeMaxDynamicSharedMemorySize, K4_SMEM);

    k_wsoft<<<BT_/64, 128, K1_SMEM>>>(q, k_emb, Mk);
    k_ea   <<<BT_/64, 128, K2_SMEM>>>(q, r, v_emb, eW, eb, aW, ab);
    k_scan <<<dim3(B_, 2), 128>>>(Mv0, out);
    k_fp   <<<BT_/64, 128, K4_SMEM>>>(fW, fb, pW, pb, out);
}

// round 2
// speedup vs baseline: 2.0941x; 2.0941x over previous
#include <cuda_runtime.h>
#include <math.h>

#define B_   64
#define T_   200
#define TP1_ 201
#define D_   128
#define M_   64
#define NQ_  13523
#define BT_  (B_*T_)          // 12800

// ---------------- scratch (no allocation allowed) ----------------
__device__ float g_k  [BT_*D_];
__device__ float g_w  [BT_*M_];
__device__ float g_e  [BT_*D_];
__device__ float g_a  [BT_*D_];
__device__ float g_rp0[BT_*D_];
__device__ float g_rp1[BT_*D_];
__device__ float g_rp2[BT_*D_];
__device__ float g_rp3[BT_*D_];

__device__ __forceinline__ float sigmoidf_(float x) { return 1.0f/(1.0f+expf(-x)); }

// ---- packed fp32x2 helpers (sm_103a FFMA2 path, PTX-only) ----
__device__ __forceinline__ unsigned long long pack2(float x, float y) {
    unsigned long long r;
    asm("mov.b64 %0, {%1, %2};" : "=l"(r) : "f"(x), "f"(y));
    return r;
}
__device__ __forceinline__ void ffma2(unsigned long long& d, unsigned long long a, unsigned long long b) {
    asm("fma.rn.f32x2 %0, %1, %2, %0;" : "+l"(d) : "l"(a), "l"(b));
}
__device__ __forceinline__ void unpack2(unsigned long long v, float& x, float& y) {
    asm("mov.b64 {%0, %1}, %2;" : "=f"(x), "=f"(y) : "l"(v));
}

// =================================================================
// Kernel 1: k gather + w = softmax(k @ Mk^T)   (also stores k to g_k)
// 64-row tile x 64 cols, 128 threads, thread tile 4x8, K chunked by 32.
// =================================================================
__global__ void __launch_bounds__(128) k_wsoft(const int* __restrict__ q,
                                               const float* __restrict__ k_emb,
                                               const float* __restrict__ Mk) {
    __shared__ __align__(16) float sxT[32*68];
    __shared__ __align__(16) float swT[32*68];
    __shared__ float sc[64*65];
    __shared__ int sq[64];
    const int tid  = threadIdx.x;
    const int row0 = blockIdx.x * 64;
    const int ti = tid & 15, tn = tid >> 4;   // rows ti*4.., cols tn*8..

    if (tid < 64) sq[tid] = q[row0 + tid];

    unsigned long long acc[4][4] = {};
    for (int kc = 0; kc < 4; kc++) {
        __syncthreads();
        // X tile (gathered) -> transposed smem, also persist to g_k
#pragma unroll
        for (int it = 0; it < 4; it++) {
            int idx = it*128 + tid;
            int row = idx >> 3;
            int k4  = (idx & 7) << 2;
            int kk  = kc*32 + k4;
            float4 v = *(const float4*)(k_emb + (size_t)sq[row]*D_ + kk);
            *(float4*)(g_k + (size_t)(row0+row)*D_ + kk) = v;
            sxT[(k4+0)*68+row]=v.x; sxT[(k4+1)*68+row]=v.y;
            sxT[(k4+2)*68+row]=v.z; sxT[(k4+3)*68+row]=v.w;
        }
        // W tile (Mk rows are output cols)
#pragma unroll
        for (int it = 0; it < 4; it++) {
            int idx = it*128 + tid;
            int n  = idx >> 3;
            int k4 = (idx & 7) << 2;
            float4 v = *(const float4*)(Mk + (size_t)n*D_ + kc*32 + k4);
            swT[(k4+0)*68+n]=v.x; swT[(k4+1)*68+n]=v.y;
            swT[(k4+2)*68+n]=v.z; swT[(k4+3)*68+n]=v.w;
        }
        __syncthreads();
#pragma unroll 8
        for (int k = 0; k < 32; k++) {
            float4 xv = *(const float4*)(sxT + k*68 + ti*4);
            ulonglong2 b0 = *(const ulonglong2*)(swT + k*68 + tn*8);
            ulonglong2 b1 = *(const ulonglong2*)(swT + k*68 + tn*8 + 4);
            unsigned long long a;
            a = pack2(xv.x, xv.x);
            ffma2(acc[0][0],a,b0.x); ffma2(acc[0][1],a,b0.y); ffma2(acc[0][2],a,b1.x); ffma2(acc[0][3],a,b1.y);
            a = pack2(xv.y, xv.y);
            ffma2(acc[1][0],a,b0.x); ffma2(acc[1][1],a,b0.y); ffma2(acc[1][2],a,b1.x); ffma2(acc[1][3],a,b1.y);
            a = pack2(xv.z, xv.z);
            ffma2(acc[2][0],a,b0.x); ffma2(acc[2][1],a,b0.y); ffma2(acc[2][2],a,b1.x); ffma2(acc[2][3],a,b1.y);
            a = pack2(xv.w, xv.w);
            ffma2(acc[3][0],a,b0.x); ffma2(acc[3][1],a,b0.y); ffma2(acc[3][2],a,b1.x); ffma2(acc[3][3],a,b1.y);
        }
    }
#pragma unroll
    for (int i = 0; i < 4; i++)
#pragma unroll
        for (int c = 0; c < 4; c++) {
            float lo, hi; unpack2(acc[i][c], lo, hi);
            sc[(ti*4+i)*65 + tn*8 + 2*c]     = lo;
            sc[(ti*4+i)*65 + tn*8 + 2*c + 1] = hi;
        }
    __syncthreads();
    if (tid < 64) {
        float mx = -1e30f;
#pragma unroll
        for (int m = 0; m < M_; m++) mx = fmaxf(mx, sc[tid*65 + m]);
        float s = 0.f;
#pragma unroll
        for (int m = 0; m < M_; m++) { float e = expf(sc[tid*65+m]-mx); sc[tid*65+m]=e; s+=e; }
        float inv = 1.0f / s;
#pragma unroll
        for (int m = 0; m < M_; m++)
            g_w[(size_t)(row0+tid)*M_ + m] = sc[tid*65+m]*inv;
    }
}

// =================================================================
// Kernel 2: v gather + e = sigmoid(v@eW^T+eb), a = tanh(v@aW^T+ab)
// grid (200, 4): y in {0,1}=eW halves, {2,3}=aW halves. 64x64 tile.
// =================================================================
__global__ void __launch_bounds__(128) k_ea(const int* __restrict__ q, const int* __restrict__ rr,
                                            const float* __restrict__ v_emb,
                                            const float* __restrict__ eW, const float* __restrict__ ebv,
                                            const float* __restrict__ aW, const float* __restrict__ abv) {
    __shared__ __align__(16) float sxT[32*68];
    __shared__ __align__(16) float swT[32*68];
    __shared__ int sq[64];
    const int tid  = threadIdx.x;
    const int row0 = blockIdx.x * 64;
    const int nc   = blockIdx.y;
    const int ti = tid & 15, tn = tid >> 4;
    const float* W    = (nc < 2) ? eW  : aW;
    const float* bias = (nc < 2) ? ebv : abv;
    const int coloff  = (nc & 1) * 64;

    if (tid < 64) { int row = row0 + tid; sq[tid] = q[row] + NQ_ * rr[row]; }

    unsigned long long acc[4][4] = {};
    for (int kc = 0; kc < 4; kc++) {
        __syncthreads();
#pragma unroll
        for (int it = 0; it < 4; it++) {
            int idx = it*128 + tid;
            int row = idx >> 3;
            int k4  = (idx & 7) << 2;
            int kk  = kc*32 + k4;
            float4 v = *(const float4*)(v_emb + (size_t)sq[row]*D_ + kk);
            sxT[(k4+0)*68+row]=v.x; sxT[(k4+1)*68+row]=v.y;
            sxT[(k4+2)*68+row]=v.z; sxT[(k4+3)*68+row]=v.w;
        }
#pragma unroll
        for (int it = 0; it < 4; it++) {
            int idx = it*128 + tid;
            int n  = idx >> 3;
            int k4 = (idx & 7) << 2;
            float4 v = *(const float4*)(W + (size_t)(coloff+n)*D_ + kc*32 + k4);
            swT[(k4+0)*68+n]=v.x; swT[(k4+1)*68+n]=v.y;
            swT[(k4+2)*68+n]=v.z; swT[(k4+3)*68+n]=v.w;
        }
        __syncthreads();
#pragma unroll 8
        for (int k = 0; k < 32; k++) {
            float4 xv = *(const float4*)(sxT + k*68 + ti*4);
            ulonglong2 b0 = *(const ulonglong2*)(swT + k*68 + tn*8);
            ulonglong2 b1 = *(const ulonglong2*)(swT + k*68 + tn*8 + 4);
            unsigned long long a;
            a = pack2(xv.x, xv.x);
            ffma2(acc[0][0],a,b0.x); ffma2(acc[0][1],a,b0.y); ffma2(acc[0][2],a,b1.x); ffma2(acc[0][3],a,b1.y);
            a = pack2(xv.y, xv.y);
            ffma2(acc[1][0],a,b0.x); ffma2(acc[1][1],a,b0.y); ffma2(acc[1][2],a,b1.x); ffma2(acc[1][3],a,b1.y);
            a = pack2(xv.z, xv.z);
            ffma2(acc[2][0],a,b0.x); ffma2(acc[2][1],a,b0.y); ffma2(acc[2][2],a,b1.x); ffma2(acc[2][3],a,b1.y);
            a = pack2(xv.w, xv.w);
            ffma2(acc[3][0],a,b0.x); ffma2(acc[3][1],a,b0.y); ffma2(acc[3][2],a,b1.x); ffma2(acc[3][3],a,b1.y);
        }
    }
    const int n0 = coloff + tn*8;
    float b[8];
#pragma unroll
    for (int j = 0; j < 8; j++) b[j] = bias[n0+j];
#pragma unroll
    for (int i = 0; i < 4; i++) {
        float y[8];
#pragma unroll
        for (int c = 0; c < 4; c++) { unpack2(acc[i][c], y[2*c], y[2*c+1]); }
        size_t row = (size_t)(row0 + ti*4 + i);
        float4 o0, o1;
        if (nc < 2) {
            o0.x=sigmoidf_(y[0]+b[0]); o0.y=sigmoidf_(y[1]+b[1]); o0.z=sigmoidf_(y[2]+b[2]); o0.w=sigmoidf_(y[3]+b[3]);
            o1.x=sigmoidf_(y[4]+b[4]); o1.y=sigmoidf_(y[5]+b[5]); o1.z=sigmoidf_(y[6]+b[6]); o1.w=sigmoidf_(y[7]+b[7]);
            *(float4*)(g_e + row*D_ + n0)     = o0;
            *(float4*)(g_e + row*D_ + n0 + 4) = o1;
        } else {
            o0.x=tanhf(y[0]+b[0]); o0.y=tanhf(y[1]+b[1]); o0.z=tanhf(y[2]+b[2]); o0.w=tanhf(y[3]+b[3]);
            o1.x=tanhf(y[4]+b[4]); o1.y=tanhf(y[5]+b[5]); o1.z=tanhf(y[6]+b[6]); o1.w=tanhf(y[7]+b[7]);
            *(float4*)(g_a + row*D_ + n0)     = o0;
            *(float4*)(g_a + row*D_ + n0 + 4) = o1;
        }
    }
}

// =================================================================
// Kernel 3: sequential scan. grid (B, 4 m-chunks of 16), 128 thr (one d each).
// State in registers; streaming stores for the 421MB Mv output.
// =================================================================
__global__ void __launch_bounds__(128) k_scan(const float* __restrict__ Mv0, float* __restrict__ out) {
    const int b   = blockIdx.x;
    const int mc  = blockIdx.y;
    const int tid = threadIdx.x;   // d
    const int m0  = mc * 16;
    __shared__ float swb[2][16];
    float Mv[16];

    float* mvout = out + BT_ + (size_t)b * TP1_ * M_ * D_;
#pragma unroll
    for (int i = 0; i < 16; i++) {
        float v = Mv0[(m0 + i) * D_ + tid];
        Mv[i] = v;
        __stcs(mvout + (size_t)(m0 + i) * D_ + tid, v);   // t = 0 slice
    }

    const float* wb  = g_w + (size_t)b * T_ * M_ + m0;
    const float* ebp = g_e + (size_t)b * T_ * D_ + tid;
    const float* abp = g_a + (size_t)b * T_ * D_ + tid;
    float* rp = ((mc==0)?g_rp0:(mc==1)?g_rp1:(mc==2)?g_rp2:g_rp3) + (size_t)b * T_ * D_ + tid;

    float wreg = 0.f;
    if (tid < 16) {
        swb[0][tid] = wb[tid];          // w_0
        wreg        = wb[M_ + tid];     // w_1 prefetched
    }
    float ecur = ebp[0], acur = abp[0];
    float* orow = mvout + (size_t)M_ * D_ + (size_t)m0 * D_ + tid;

    for (int t = 0; t < T_; t++) {
        float enx = ecur, anx = acur;
        if (t + 1 < T_) { enx = ebp[(size_t)(t+1)*D_]; anx = abp[(size_t)(t+1)*D_]; }
        __syncthreads();
        if (tid < 16) {
            if (t + 1 < T_) swb[(t+1)&1][tid] = wreg;
            if (t + 2 < T_) wreg = wb[(size_t)(t+2)*M_ + tid];
        }
        const float* wrow = swb[t & 1];
        float racc = 0.f;
#pragma unroll
        for (int i = 0; i < 16; i++) {
            float wv = wrow[i];
            racc  = fmaf(wv, Mv[i], racc);                            // read uses OLD Mv
            Mv[i] = fmaf(wv, acur, Mv[i] * fmaf(-wv, ecur, 1.0f));
            __stcs(orow + (size_t)i * D_, Mv[i]);
        }
        rp[(size_t)t * D_] = racc;
        ecur = enx; acur = anx;
        orow += (size_t)M_ * D_;
    }
}

// =================================================================
// Kernel 4: read = sum(rp0..3); f = tanh([read,k]@fW^T + fb);
// p = sigmoid(f . pW + pb). 64 rows x 128 cols per CTA, 256 threads.
// =================================================================
__global__ void __launch_bounds__(256) k_fp(const float* __restrict__ fW, const float* __restrict__ fb,
                                            const float* __restrict__ pW, const float* __restrict__ pb,
                                            float* __restrict__ out) {
    __shared__ __align__(16) float sxT[32*68];
    __shared__ __align__(16) float swT[32*132];
    __shared__ float sp[64*17];
    const int tid  = threadIdx.x;
    const int row0 = blockIdx.x * 64;
    const int ti = tid & 15, tn = tid >> 4;   // tn 0..15 -> cols tn*8..

    unsigned long long acc[4][4] = {};
    for (int kc = 0; kc < 8; kc++) {
        __syncthreads();
        // X tile: cols 0..127 = read (sum of 4 partials), 128..255 = k
#pragma unroll
        for (int it = 0; it < 2; it++) {
            int idx = it*256 + tid;
            int row = idx >> 3;
            int k4  = (idx & 7) << 2;
            int kk  = kc*32 + k4;
            float4 v;
            if (kc < 4) {
                size_t g = (size_t)(row0+row)*D_ + kk;
                float4 a0 = *(const float4*)(g_rp0+g);
                float4 a1 = *(const float4*)(g_rp1+g);
                float4 a2 = *(const float4*)(g_rp2+g);
                float4 a3 = *(const float4*)(g_rp3+g);
                v.x=(a0.x+a1.x)+(a2.x+a3.x); v.y=(a0.y+a1.y)+(a2.y+a3.y);
                v.z=(a0.z+a1.z)+(a2.z+a3.z); v.w=(a0.w+a1.w)+(a2.w+a3.w);
            } else {
                v = *(const float4*)(g_k + (size_t)(row0+row)*D_ + (kk-128));
            }
            sxT[(k4+0)*68+row]=v.x; sxT[(k4+1)*68+row]=v.y;
            sxT[(k4+2)*68+row]=v.z; sxT[(k4+3)*68+row]=v.w;
        }
#pragma unroll
        for (int it = 0; it < 4; it++) {
            int idx = it*256 + tid;
            int n  = idx >> 3;
            int k4 = (idx & 7) << 2;
            float4 v = *(const float4*)(fW + (size_t)n*256 + kc*32 + k4);
            swT[(k4+0)*132+n]=v.x; swT[(k4+1)*132+n]=v.y;
            swT[(k4+2)*132+n]=v.z; swT[(k4+3)*132+n]=v.w;
        }
        __syncthreads();
#pragma unroll 8
        for (int k = 0; k < 32; k++) {
            float4 xv = *(const float4*)(sxT + k*68 + ti*4);
            ulonglong2 b0 = *(const ulonglong2*)(swT + k*132 + tn*8);
            ulonglong2 b1 = *(const ulonglong2*)(swT + k*132 + tn*8 + 4);
            unsigned long long a;
            a = pack2(xv.x, xv.x);
            ffma2(acc[0][0],a,b0.x); ffma2(acc[0][1],a,b0.y); ffma2(acc[0][2],a,b1.x); ffma2(acc[0][3],a,b1.y);
            a = pack2(xv.y, xv.y);
            ffma2(acc[1][0],a,b0.x); ffma2(acc[1][1],a,b0.y); ffma2(acc[1][2],a,b1.x); ffma2(acc[1][3],a,b1.y);
            a = pack2(xv.z, xv.z);
            ffma2(acc[2][0],a,b0.x); ffma2(acc[2][1],a,b0.y); ffma2(acc[2][2],a,b1.x); ffma2(acc[2][3],a,b1.y);
            a = pack2(xv.w, xv.w);
            ffma2(acc[3][0],a,b0.x); ffma2(acc[3][1],a,b0.y); ffma2(acc[3][2],a,b1.x); ffma2(acc[3][3],a,b1.y);
        }
    }
    // epilogue: f = tanh(acc + fb), partial p = sum pW*f
    float ps[4] = {0.f, 0.f, 0.f, 0.f};
#pragma unroll
    for (int c = 0; c < 4; c++) {
        int n = tn*8 + 2*c;
        float blo = fb[n], bhi = fb[n+1];
        float wlo = pW[n], whi = pW[n+1];
#pragma unroll
        for (int i = 0; i < 4; i++) {
            float lo, hi; unpack2(acc[i][c], lo, hi);
            ps[i] = fmaf(wlo, tanhf(lo + blo), ps[i]);
            ps[i] = fmaf(whi, tanhf(hi + bhi), ps[i]);
        }
    }
#pragma unroll
    for (int i = 0; i < 4; i++) sp[(ti*4+i)*17 + tn] = ps[i];
    __syncthreads();
    if (tid < 64) {
        float s = pb[0];
#pragma unroll
        for (int g2 = 0; g2 < 16; g2++) s += sp[tid*17 + g2];
        out[row0 + tid] = 1.0f / (1.0f + expf(-s));
    }
}

// =================================================================
extern "C" void kernel_launch(void* const* d_in, const int* in_sizes, int n_in,
                              void* d_out, int out_size) {
    const int*   q     = (const int*)  d_in[0];
    const int*   r     = (const int*)  d_in[1];
    const float* k_emb = (const float*)d_in[2];
    const float* v_emb = (const float*)d_in[3];
    const float* Mk    = (const float*)d_in[4];
    const float* Mv0   = (const float*)d_in[5];
    const float* fW    = (const float*)d_in[6];
    const float* fb    = (const float*)d_in[7];
    const float* pW    = (const float*)d_in[8];
    const float* pb    = (const float*)d_in[9];
    const float* eW    = (const float*)d_in[10];
    const float* eb    = (const float*)d_in[11];
    const float* aW    = (const float*)d_in[12];
    const float* ab    = (const float*)d_in[13];
    float* out = (float*)d_out;

    k_wsoft<<<BT_/64, 128>>>(q, k_emb, Mk);
    k_ea   <<<dim3(BT_/64, 4), 128>>>(q, r, v_emb, eW, eb, aW, ab);
    k_scan <<<dim3(B_, 4), 128>>>(Mv0, out);
    k_fp   <<<BT_/64, 256>>>(fW, fb, pW, pb, out);
}

// round 5
// speedup vs baseline: 2.3863x; 1.1395x over previous
#include <cuda_runtime.h>
#include <math.h>

#define B_   64
#define T_   200
#define TP1_ 201
#define D_   128
#define M_   64
#define NQ_  13523
#define BT_  (B_*T_)          // 12800

// ---------------- scratch (no allocation allowed) ----------------
__device__ float g_k  [BT_*D_];
__device__ float g_w  [BT_*M_];
__device__ float g_e  [BT_*D_];
__device__ float g_a  [BT_*D_];
__device__ float g_rp0[BT_*D_];
__device__ float g_rp1[BT_*D_];
__device__ float g_rp2[BT_*D_];
__device__ float g_rp3[BT_*D_];

__device__ __forceinline__ float sigmoidf_(float x) { return 1.0f/(1.0f+expf(-x)); }

// ---- packed fp32x2 helpers (sm_103a FFMA2 path, PTX-only) ----
__device__ __forceinline__ unsigned long long pack2(float x, float y) {
    unsigned long long r;
    asm("mov.b64 %0, {%1, %2};" : "=l"(r) : "f"(x), "f"(y));
    return r;
}
__device__ __forceinline__ void ffma2(unsigned long long& d, unsigned long long a, unsigned long long b) {
    asm("fma.rn.f32x2 %0, %1, %2, %0;" : "+l"(d) : "l"(a), "l"(b));
}
__device__ __forceinline__ void unpack2(unsigned long long v, float& x, float& y) {
    asm("mov.b64 {%0, %1}, %2;" : "=f"(x), "=f"(y) : "l"(v));
}

// shared inner product step: 4 rows x 8 cols, one k
__device__ __forceinline__ void mm_step(unsigned long long acc[4][4],
                                        const float* sxT, const float* swT,
                                        int xstride, int wstride, int k, int ti, int tn) {
    float4 xv = *(const float4*)(sxT + k*xstride + ti*4);
    ulonglong2 b0 = *(const ulonglong2*)(swT + k*wstride + tn*8);
    ulonglong2 b1 = *(const ulonglong2*)(swT + k*wstride + tn*8 + 4);
    unsigned long long a;
    a = pack2(xv.x, xv.x);
    ffma2(acc[0][0],a,b0.x); ffma2(acc[0][1],a,b0.y); ffma2(acc[0][2],a,b1.x); ffma2(acc[0][3],a,b1.y);
    a = pack2(xv.y, xv.y);
    ffma2(acc[1][0],a,b0.x); ffma2(acc[1][1],a,b0.y); ffma2(acc[1][2],a,b1.x); ffma2(acc[1][3],a,b1.y);
    a = pack2(xv.z, xv.z);
    ffma2(acc[2][0],a,b0.x); ffma2(acc[2][1],a,b0.y); ffma2(acc[2][2],a,b1.x); ffma2(acc[2][3],a,b1.y);
    a = pack2(xv.w, xv.w);
    ffma2(acc[3][0],a,b0.x); ffma2(acc[3][1],a,b0.y); ffma2(acc[3][2],a,b1.x); ffma2(acc[3][3],a,b1.y);
}

// =================================================================
// Merged kernel: grid (200, 5). y==0 -> wsoft (k gather + softmax(k@Mk^T))
//                               y in 1..4 -> e/a GEMMs.
// Software-pipelined: prefetch next K-chunk into regs during compute.
// =================================================================
#define SM_SXT 0
#define SM_SWT (32*68)
#define SM_AUX (2*32*68)          // ea: sq ; wsoft: sc[64*65] then sq
#define SM_TOTAL (SM_AUX + 64*65 + 64)

__global__ void __launch_bounds__(128) k_we(const int* __restrict__ q, const int* __restrict__ rr,
                                            const float* __restrict__ k_emb, const float* __restrict__ Mk,
                                            const float* __restrict__ v_emb,
                                            const float* __restrict__ eW, const float* __restrict__ ebv,
                                            const float* __restrict__ aW, const float* __restrict__ abv) {
    __shared__ __align__(16) float smbuf[SM_TOTAL];
    float* sxT = smbuf + SM_SXT;
    float* swT = smbuf + SM_SWT;
    const int tid  = threadIdx.x;
    const int row0 = blockIdx.x * 64;
    const int yb   = blockIdx.y;
    const int ti = tid & 15, tn = tid >> 4;

    // per-it decoded indices (same for X and W: 4 float4s per thread per chunk)
    int rA[4], kA[4];
#pragma unroll
    for (int it = 0; it < 4; it++) {
        int idx = it*128 + tid;
        rA[it] = idx >> 3;
        kA[it] = (idx & 7) << 2;
    }

    if (yb == 0) {
        // ---------------- wsoft ----------------
        float* sc = smbuf + SM_AUX;
        int*   sq = (int*)(smbuf + SM_AUX + 64*65);
        if (tid < 64) sq[tid] = q[row0 + tid];
        __syncthreads();

        float4 xr[4], wr[4];
#pragma unroll
        for (int it = 0; it < 4; it++) {
            xr[it] = *(const float4*)(k_emb + (size_t)sq[rA[it]]*D_ + kA[it]);
            wr[it] = *(const float4*)(Mk    + (size_t)rA[it]*D_ + kA[it]);
        }
        unsigned long long acc[4][4] = {};
        for (int kc = 0; kc < 4; kc++) {
            if (kc) __syncthreads();
#pragma unroll
            for (int it = 0; it < 4; it++) {
                int k4 = kA[it], row = rA[it];
                sxT[(k4+0)*68+row]=xr[it].x; sxT[(k4+1)*68+row]=xr[it].y;
                sxT[(k4+2)*68+row]=xr[it].z; sxT[(k4+3)*68+row]=xr[it].w;
                swT[(k4+0)*68+row]=wr[it].x; swT[(k4+1)*68+row]=wr[it].y;
                swT[(k4+2)*68+row]=wr[it].z; swT[(k4+3)*68+row]=wr[it].w;
                // persist gathered k
                *(float4*)(g_k + (size_t)(row0+row)*D_ + kc*32 + k4) = xr[it];
            }
            __syncthreads();
            if (kc < 3) {
                int kk = (kc+1)*32;
#pragma unroll
                for (int it = 0; it < 4; it++) {
                    xr[it] = *(const float4*)(k_emb + (size_t)sq[rA[it]]*D_ + kk + kA[it]);
                    wr[it] = *(const float4*)(Mk    + (size_t)rA[it]*D_ + kk + kA[it]);
                }
            }
#pragma unroll 8
            for (int k = 0; k < 32; k++) mm_step(acc, sxT, swT, 68, 68, k, ti, tn);
        }
#pragma unroll
        for (int i = 0; i < 4; i++)
#pragma unroll
            for (int c = 0; c < 4; c++) {
                float lo, hi; unpack2(acc[i][c], lo, hi);
                sc[(ti*4+i)*65 + tn*8 + 2*c]     = lo;
                sc[(ti*4+i)*65 + tn*8 + 2*c + 1] = hi;
            }
        __syncthreads();
        if (tid < 64) {
            float mx = -1e30f;
#pragma unroll
            for (int m = 0; m < M_; m++) mx = fmaxf(mx, sc[tid*65 + m]);
            float s = 0.f;
#pragma unroll
            for (int m = 0; m < M_; m++) { float e = expf(sc[tid*65+m]-mx); sc[tid*65+m]=e; s+=e; }
            float inv = 1.0f / s;
#pragma unroll
            for (int m = 0; m < M_; m++)
                g_w[(size_t)(row0+tid)*M_ + m] = sc[tid*65+m]*inv;
        }
    } else {
        // ---------------- e/a GEMM ----------------
        const int nc = yb - 1;
        int* sq = (int*)(smbuf + SM_AUX);
        const float* W    = (nc < 2) ? eW  : aW;
        const float* bias = (nc < 2) ? ebv : abv;
        const int coloff  = (nc & 1) * 64;
        if (tid < 64) { int row = row0 + tid; sq[tid] = q[row] + NQ_ * rr[row]; }
        __syncthreads();

        float4 xr[4], wr[4];
#pragma unroll
        for (int it = 0; it < 4; it++) {
            xr[it] = *(const float4*)(v_emb + (size_t)sq[rA[it]]*D_ + kA[it]);
            wr[it] = *(const float4*)(W + (size_t)(coloff + rA[it])*D_ + kA[it]);
        }
        unsigned long long acc[4][4] = {};
        for (int kc = 0; kc < 4; kc++) {
            if (kc) __syncthreads();
#pragma unroll
            for (int it = 0; it < 4; it++) {
                int k4 = kA[it], row = rA[it];
                sxT[(k4+0)*68+row]=xr[it].x; sxT[(k4+1)*68+row]=xr[it].y;
                sxT[(k4+2)*68+row]=xr[it].z; sxT[(k4+3)*68+row]=xr[it].w;
                swT[(k4+0)*68+row]=wr[it].x; swT[(k4+1)*68+row]=wr[it].y;
                swT[(k4+2)*68+row]=wr[it].z; swT[(k4+3)*68+row]=wr[it].w;
            }
            __syncthreads();
            if (kc < 3) {
                int kk = (kc+1)*32;
#pragma unroll
                for (int it = 0; it < 4; it++) {
                    xr[it] = *(const float4*)(v_emb + (size_t)sq[rA[it]]*D_ + kk + kA[it]);
                    wr[it] = *(const float4*)(W + (size_t)(coloff + rA[it])*D_ + kk + kA[it]);
                }
            }
#pragma unroll 8
            for (int k = 0; k < 32; k++) mm_step(acc, sxT, swT, 68, 68, k, ti, tn);
        }
        const int n0 = coloff + tn*8;
        float b[8];
#pragma unroll
        for (int j = 0; j < 8; j++) b[j] = bias[n0+j];
#pragma unroll
        for (int i = 0; i < 4; i++) {
            float y[8];
#pragma unroll
            for (int c = 0; c < 4; c++) { unpack2(acc[i][c], y[2*c], y[2*c+1]); }
            size_t row = (size_t)(row0 + ti*4 + i);
            float4 o0, o1;
            if (nc < 2) {
                o0.x=sigmoidf_(y[0]+b[0]); o0.y=sigmoidf_(y[1]+b[1]); o0.z=sigmoidf_(y[2]+b[2]); o0.w=sigmoidf_(y[3]+b[3]);
                o1.x=sigmoidf_(y[4]+b[4]); o1.y=sigmoidf_(y[5]+b[5]); o1.z=sigmoidf_(y[6]+b[6]); o1.w=sigmoidf_(y[7]+b[7]);
                *(float4*)(g_e + row*D_ + n0)     = o0;
                *(float4*)(g_e + row*D_ + n0 + 4) = o1;
            } else {
                o0.x=tanhf(y[0]+b[0]); o0.y=tanhf(y[1]+b[1]); o0.z=tanhf(y[2]+b[2]); o0.w=tanhf(y[3]+b[3]);
                o1.x=tanhf(y[4]+b[4]); o1.y=tanhf(y[5]+b[5]); o1.z=tanhf(y[6]+b[6]); o1.w=tanhf(y[7]+b[7]);
                *(float4*)(g_a + row*D_ + n0)     = o0;
                *(float4*)(g_a + row*D_ + n0 + 4) = o1;
            }
        }
    }
}

// =================================================================
// Kernel 3: sequential scan. grid (B, 4 m-chunks of 16), 128 thr (one d each).
// NO block syncs: w broadcast via direct LDG (L1 broadcast), prefetched 1 step.
// =================================================================
__global__ void __launch_bounds__(128) k_scan(const float* __restrict__ Mv0, float* __restrict__ out) {
    const int b   = blockIdx.x;
    const int mc  = blockIdx.y;
    const int tid = threadIdx.x;   // d
    const int m0  = mc * 16;
    float Mv[16];

    float* mvout = out + BT_ + (size_t)b * TP1_ * M_ * D_;
#pragma unroll
    for (int i = 0; i < 16; i++) {
        float v = Mv0[(m0 + i) * D_ + tid];
        Mv[i] = v;
        __stcs(mvout + (size_t)(m0 + i) * D_ + tid, v);   // t = 0 slice
    }

    const float* wb  = g_w + (size_t)b * T_ * M_ + m0;
    const float* ebp = g_e + (size_t)b * T_ * D_ + tid;
    const float* abp = g_a + (size_t)b * T_ * D_ + tid;
    float* rp = ((mc==0)?g_rp0:(mc==1)?g_rp1:(mc==2)?g_rp2:g_rp3) + (size_t)b * T_ * D_ + tid;

    float4 w0 = *(const float4*)(wb);
    float4 w1 = *(const float4*)(wb + 4);
    float4 w2 = *(const float4*)(wb + 8);
    float4 w3 = *(const float4*)(wb + 12);
    float ecur = ebp[0], acur = abp[0];
    float* orow = mvout + (size_t)M_ * D_ + (size_t)m0 * D_ + tid;

    for (int t = 0; t < T_; t++) {
        float4 nw0=w0, nw1=w1, nw2=w2, nw3=w3;
        float enx = ecur, anx = acur;
        if (t + 1 < T_) {
            const float* wn = wb + (size_t)(t+1)*M_;
            nw0 = *(const float4*)(wn);     nw1 = *(const float4*)(wn + 4);
            nw2 = *(const float4*)(wn + 8); nw3 = *(const float4*)(wn + 12);
            enx = ebp[(size_t)(t+1)*D_];
            anx = abp[(size_t)(t+1)*D_];
        }
        float wv[16] = {w0.x,w0.y,w0.z,w0.w, w1.x,w1.y,w1.z,w1.w,
                        w2.x,w2.y,w2.z,w2.w, w3.x,w3.y,w3.z,w3.w};
        float r0=0.f, r1=0.f;
#pragma unroll
        for (int i = 0; i < 16; i++) {
            float wvi = wv[i];
            if (i & 1) r1 = fmaf(wvi, Mv[i], r1); else r0 = fmaf(wvi, Mv[i], r0);
            Mv[i] = fmaf(wvi, acur, Mv[i] * fmaf(-wvi, ecur, 1.0f));    // Mv*(1-w e)+w a
            __stcs(orow + (size_t)i * D_, Mv[i]);
        }
        rp[(size_t)t * D_] = r0 + r1;
        w0=nw0; w1=nw1; w2=nw2; w3=nw3;
        ecur = enx; acur = anx;
        orow += (size_t)M_ * D_;
    }
}

// =================================================================
// Kernel 4: read = sum(rp0..3); f = tanh([read,k]@fW^T + fb);
// p = sigmoid(f . pW + pb). 64 rows x 128 cols per CTA, 256 threads.
// Software-pipelined like k_we.
// =================================================================
__global__ void __launch_bounds__(256) k_fp(const float* __restrict__ fW, const float* __restrict__ fb,
                                            const float* __restrict__ pW, const float* __restrict__ pb,
                                            float* __restrict__ out) {
    __shared__ __align__(16) float sxT[32*68];
    __shared__ __align__(16) float swT[32*132];
    __shared__ float sp[64*17];
    const int tid  = threadIdx.x;
    const int row0 = blockIdx.x * 64;
    const int ti = tid & 15, tn = tid >> 4;   // tn 0..15 -> cols tn*8..

    int rA[2], kA[2], nB[4], kB[4];
#pragma unroll
    for (int it = 0; it < 2; it++) {
        int idx = it*256 + tid;
        rA[it] = idx >> 3; kA[it] = (idx & 7) << 2;
    }
#pragma unroll
    for (int it = 0; it < 4; it++) {
        int idx = it*256 + tid;
        nB[it] = idx >> 3; kB[it] = (idx & 7) << 2;
    }

    auto loadX = [&](int row, int kk) -> float4 {
        if (kk < 128) {
            size_t g = (size_t)(row0+row)*D_ + kk;
            float4 a0 = *(const float4*)(g_rp0+g);
            float4 a1 = *(const float4*)(g_rp1+g);
            float4 a2 = *(const float4*)(g_rp2+g);
            float4 a3 = *(const float4*)(g_rp3+g);
            float4 v;
            v.x=(a0.x+a1.x)+(a2.x+a3.x); v.y=(a0.y+a1.y)+(a2.y+a3.y);
            v.z=(a0.z+a1.z)+(a2.z+a3.z); v.w=(a0.w+a1.w)+(a2.w+a3.w);
            return v;
        }
        return *(const float4*)(g_k + (size_t)(row0+row)*D_ + (kk-128));
    };

    float4 xr[2], wr[4];
#pragma unroll
    for (int it = 0; it < 2; it++) xr[it] = loadX(rA[it], kA[it]);
#pragma unroll
    for (int it = 0; it < 4; it++) wr[it] = *(const float4*)(fW + (size_t)nB[it]*256 + kB[it]);

    unsigned long long acc[4][4] = {};
    for (int kc = 0; kc < 8; kc++) {
        if (kc) __syncthreads();
#pragma unroll
        for (int it = 0; it < 2; it++) {
            int k4 = kA[it], row = rA[it];
            sxT[(k4+0)*68+row]=xr[it].x; sxT[(k4+1)*68+row]=xr[it].y;
            sxT[(k4+2)*68+row]=xr[it].z; sxT[(k4+3)*68+row]=xr[it].w;
        }
#pragma unroll
        for (int it = 0; it < 4; it++) {
            int k4 = kB[it], n = nB[it];
            swT[(k4+0)*132+n]=wr[it].x; swT[(k4+1)*132+n]=wr[it].y;
            swT[(k4+2)*132+n]=wr[it].z; swT[(k4+3)*132+n]=wr[it].w;
        }
        __syncthreads();
        if (kc < 7) {
            int kk = (kc+1)*32;
#pragma unroll
            for (int it = 0; it < 2; it++) xr[it] = loadX(rA[it], kk + kA[it]);
#pragma unroll
            for (int it = 0; it < 4; it++) wr[it] = *(const float4*)(fW + (size_t)nB[it]*256 + kk + kB[it]);
        }
#pragma unroll 8
        for (int k = 0; k < 32; k++) mm_step(acc, sxT, swT, 68, 132, k, ti, tn);
    }

    // epilogue: f = tanh(acc + fb), partial p = sum pW*f
    float ps[4] = {0.f, 0.f, 0.f, 0.f};
#pragma unroll
    for (int c = 0; c < 4; c++) {
        int n = tn*8 + 2*c;
        float blo = fb[n], bhi = fb[n+1];
        float wlo = pW[n], whi = pW[n+1];
#pragma unroll
        for (int i = 0; i < 4; i++) {
            float lo, hi; unpack2(acc[i][c], lo, hi);
            ps[i] = fmaf(wlo, tanhf(lo + blo), ps[i]);
            ps[i] = fmaf(whi, tanhf(hi + bhi), ps[i]);
        }
    }
#pragma unroll
    for (int i = 0; i < 4; i++) sp[(ti*4+i)*17 + tn] = ps[i];
    __syncthreads();
    if (tid < 64) {
        float s = pb[0];
#pragma unroll
        for (int g2 = 0; g2 < 16; g2++) s += sp[tid*17 + g2];
        out[row0 + tid] = 1.0f / (1.0f + expf(-s));
    }
}

// =================================================================
extern "C" void kernel_launch(void* const* d_in, const int* in_sizes, int n_in,
                              void* d_out, int out_size) {
    const int*   q     = (const int*)  d_in[0];
    const int*   r     = (const int*)  d_in[1];
    const float* k_emb = (const float*)d_in[2];
    const float* v_emb = (const float*)d_in[3];
    const float* Mk    = (const float*)d_in[4];
    const float* Mv0   = (const float*)d_in[5];
    const float* fW    = (const float*)d_in[6];
    const float* fb    = (const float*)d_in[7];
    const float* pW    = (const float*)d_in[8];
    const float* pb    = (const float*)d_in[9];
    const float* eW    = (const float*)d_in[10];
    const float* eb    = (const float*)d_in[11];
    const float* aW    = (const float*)d_in[12];
    const float* ab    = (const float*)d_in[13];
    float* out = (float*)d_out;

    k_we   <<<dim3(BT_/64, 5), 128>>>(q, r, k_emb, Mk, v_emb, eW, eb, aW, ab);
    k_scan <<<dim3(B_, 4), 128>>>(Mv0, out);
    k_fp   <<<BT_/64, 256>>>(fW, fb, pW, pb, out);
}